// round 7
// baseline (speedup 1.0000x reference)
#include <cuda_runtime.h>
#include <cstdint>

#define TT   512
#define BB   1024
#define H1   64
#define G1   256     // 4*H1
#define BT1  8
#define H2   32
#define G2   128     // 4*H2
#define BT2  4

typedef unsigned long long ull;

// scratch: h1[t][b][j], j in [0,128): fwd half [0,64), rev half [64,128)
__device__ float g_h1[(size_t)TT * BB * 128];

// ---- fast activations -----------------------------------------------------
__device__ __forceinline__ float tanh_(float x) {
    float y;
    asm("tanh.approx.f32 %0, %1;" : "=f"(y) : "f"(x));
    return y;
}
__device__ __forceinline__ float sigm(float x) {
    return fmaf(tanh_(x * 0.5f), 0.5f, 0.5f);
}

// ---- packed fp32x2 fma ----------------------------------------------------
__device__ __forceinline__ void ffma2(ull& acc, ull a, ull b) {
    asm("fma.rn.f32x2 %0, %1, %2, %0;" : "+l"(acc) : "l"(a), "l"(b));
}
__device__ __forceinline__ ull pack2(float lo, float hi) {
    ull r;
    asm("mov.b64 %0, {%1, %2};" : "=l"(r) : "f"(lo), "f"(hi));
    return r;
}
__device__ __forceinline__ float hadd2(ull v) {
    float lo, hi;
    asm("mov.b64 {%0, %1}, %2;" : "=f"(lo), "=f"(hi) : "l"(v));
    return lo + hi;
}

// ---------------------------------------------------------------------------
// Kernel 1: bidirectional layer-1 LSTM, two-phase pipeline, 4 gates/thread.
// grid = (128, 2), block = 256.  thread = (gq = tid&63, ks = tid>>6).
// Thread owns gates 4gq..4gq+3, k-slice [16ks, 16ks+16).
// Batch halves: A = rows 0..3, B = rows 4..7.
// Step t: P1 = cell(B,t-1) + FMA(A,t);  P2 = cell(A,t) + FMA(B,t).
// ---------------------------------------------------------------------------
__global__ __launch_bounds__(256, 2)
void lstm1_kernel(const float* __restrict__ x,
                  const float* __restrict__ wih_f, const float* __restrict__ whh_f,
                  const float* __restrict__ b_f,
                  const float* __restrict__ wih_r, const float* __restrict__ whh_r,
                  const float* __restrict__ b_r)
{
    const int dir = blockIdx.y;
    const int b0  = blockIdx.x * BT1;
    const int tid = threadIdx.x;
    const int gq  = tid & 63;
    const int ks  = tid >> 6;

    const float* wih = dir ? wih_r : wih_f;
    const float* whh = dir ? whh_r : whh_f;
    const float* bb  = dir ? b_r  : b_f;

    __shared__ float sxc[BT1][64];       // 2 KB: x chunk (64 timesteps)
    __shared__ float sh[BT1][H1];        // 2 KB: current h
    __shared__ float sz[4][BT1][G1];     // 32 KB: per-k-slice gate partials

    for (int i = tid; i < BT1 * H1; i += 256) ((float*)sh)[i] = 0.f;

    // weights: 4 gate rows x 16 k = 32 packed k-pairs (64 regs)
    ull wp[4][8];
#pragma unroll
    for (int g = 0; g < 4; g++) {
        const ull* wr = (const ull*)(whh + (4 * gq + g) * H1 + 16 * ks);
#pragma unroll
        for (int j = 0; j < 8; j++) wp[g][j] = wr[j];
    }
    float wi[4], bs[4];
#pragma unroll
    for (int g = 0; g < 4; g++) {
        wi[g] = (ks == 0) ? wih[4 * gq + g] : 0.f;
        bs[g] = (ks == 0) ? bb[4 * gq + g]  : 0.f;
    }

    // cell states: c0 for (cb, ch) in half A, c1 for (cb+4, ch) in half B
    float c0 = 0.f, c1 = 0.f;
    const int cb = tid >> 6;            // 0..3
    const int ch = tid & 63;

    __syncthreads();

    for (int tt = 0; tt < TT; ++tt) {
        const int t = dir ? (TT - 1 - tt) : tt;

        if ((tt & 63) == 0) {
            const int tbase = dir ? (448 - tt) : tt;
            for (int i = tid; i < BT1 * 64; i += 256) {
                int b = i >> 6, to = i & 63;
                sxc[b][to] = x[(size_t)(b0 + b) * TT + tbase + to];
            }
            __syncthreads();
        }
        const int ts = t & 63;

        // ================= P1: cell(B, t-1) + FMA(A, t) =================
        if (tt > 0) {
            const int tp  = dir ? (TT - tt) : (tt - 1);
            const int cb2 = cb + 4;
            float zi = 0.f, zf = 0.f, zg = 0.f, zo = 0.f;
#pragma unroll
            for (int s = 0; s < 4; s++) {
                zi += sz[s][cb2][ch];
                zf += sz[s][cb2][64 + ch];
                zg += sz[s][cb2][128 + ch];
                zo += sz[s][cb2][192 + ch];
            }
            c1 = sigm(zf) * c1 + sigm(zi) * tanh_(zg);
            float hv = sigm(zo) * tanh_(c1);
            sh[cb2][ch] = hv;
            g_h1[((size_t)tp * BB + (b0 + cb2)) * 128 + dir * 64 + ch] = hv;
        }
        {
            ull acc[4][4];   // [gate][batch]
            if (ks == 0) {
#pragma unroll
                for (int b = 0; b < 4; b++) {
                    float xv = sxc[b][ts];
#pragma unroll
                    for (int g = 0; g < 4; g++)
                        acc[g][b] = pack2(fmaf(xv, wi[g], bs[g]), 0.f);
                }
            } else {
#pragma unroll
                for (int b = 0; b < 4; b++)
#pragma unroll
                    for (int g = 0; g < 4; g++) acc[g][b] = 0ULL;
            }
#pragma unroll
            for (int j = 0; j < 4; j++) {
#pragma unroll
                for (int b = 0; b < 4; b++) {
                    ulonglong2 hv = *(const ulonglong2*)&sh[b][16 * ks + 4 * j];
#pragma unroll
                    for (int g = 0; g < 4; g++) {
                        ffma2(acc[g][b], hv.x, wp[g][2 * j]);
                        ffma2(acc[g][b], hv.y, wp[g][2 * j + 1]);
                    }
                }
            }
#pragma unroll
            for (int b = 0; b < 4; b++) {
                float4 v = make_float4(hadd2(acc[0][b]), hadd2(acc[1][b]),
                                       hadd2(acc[2][b]), hadd2(acc[3][b]));
                *(float4*)&sz[ks][b][4 * gq] = v;
            }
        }
        __syncthreads();

        // ================= P2: cell(A, t) + FMA(B, t) =================
        {
            float zi = 0.f, zf = 0.f, zg = 0.f, zo = 0.f;
#pragma unroll
            for (int s = 0; s < 4; s++) {
                zi += sz[s][cb][ch];
                zf += sz[s][cb][64 + ch];
                zg += sz[s][cb][128 + ch];
                zo += sz[s][cb][192 + ch];
            }
            c0 = sigm(zf) * c0 + sigm(zi) * tanh_(zg);
            float hv = sigm(zo) * tanh_(c0);
            sh[cb][ch] = hv;
            g_h1[((size_t)t * BB + (b0 + cb)) * 128 + dir * 64 + ch] = hv;
        }
        {
            ull acc[4][4];
            if (ks == 0) {
#pragma unroll
                for (int b = 0; b < 4; b++) {
                    float xv = sxc[b + 4][ts];
#pragma unroll
                    for (int g = 0; g < 4; g++)
                        acc[g][b] = pack2(fmaf(xv, wi[g], bs[g]), 0.f);
                }
            } else {
#pragma unroll
                for (int b = 0; b < 4; b++)
#pragma unroll
                    for (int g = 0; g < 4; g++) acc[g][b] = 0ULL;
            }
#pragma unroll
            for (int j = 0; j < 4; j++) {
#pragma unroll
                for (int b = 0; b < 4; b++) {
                    ulonglong2 hv = *(const ulonglong2*)&sh[b + 4][16 * ks + 4 * j];
#pragma unroll
                    for (int g = 0; g < 4; g++) {
                        ffma2(acc[g][b], hv.x, wp[g][2 * j]);
                        ffma2(acc[g][b], hv.y, wp[g][2 * j + 1]);
                    }
                }
            }
#pragma unroll
            for (int b = 0; b < 4; b++) {
                float4 v = make_float4(hadd2(acc[0][b]), hadd2(acc[1][b]),
                                       hadd2(acc[2][b]), hadd2(acc[3][b]));
                *(float4*)&sz[ks][b + 4][4 * gq] = v;
            }
        }
        __syncthreads();
    }

    // epilogue: cell(B, t_last)
    {
        const int tp  = dir ? 0 : (TT - 1);
        const int cb2 = cb + 4;
        float zi = 0.f, zf = 0.f, zg = 0.f, zo = 0.f;
#pragma unroll
        for (int s = 0; s < 4; s++) {
            zi += sz[s][cb2][ch];
            zf += sz[s][cb2][64 + ch];
            zg += sz[s][cb2][128 + ch];
            zo += sz[s][cb2][192 + ch];
        }
        c1 = sigm(zf) * c1 + sigm(zi) * tanh_(zg);
        float hv = sigm(zo) * tanh_(c1);
        g_h1[((size_t)tp * BB + (b0 + cb2)) * 128 + dir * 64 + ch] = hv;
    }
}

// ---------------------------------------------------------------------------
// Kernel 2: layer-2 forward scan + single reverse step + MLP head,
// two-phase pipeline, 4 gates/thread.
// grid = 256, block = 256.  thread = (gq = tid&31, ks = tid>>5 in 0..7).
// Thread owns gates 4gq..4gq+3; combined k-dim 160 (128 inp + 32 rec),
// slice [20ks, 20ks+20).  buf row = [0,128) h1 input, [128,160) h2.
// Batch halves: A = rows {0,1}, B = rows {2,3}.
// ---------------------------------------------------------------------------
__global__ __launch_bounds__(256, 2)
void lstm2_kernel(const float* __restrict__ wih2f, const float* __restrict__ whh2f,
                  const float* __restrict__ b2f,
                  const float* __restrict__ wih2r, const float* __restrict__ b2r,
                  const float* __restrict__ w_fc1, const float* __restrict__ b_fc1,
                  const float* __restrict__ w_out, const float* __restrict__ b_out,
                  float* __restrict__ out)
{
    const int b0  = blockIdx.x * BT2;
    const int tid = threadIdx.x;
    const int gq  = tid & 31;
    const int ks  = tid >> 5;

    __shared__ float buf[2][BT2][160];   // 5 KB: double-buffered combined rows
    __shared__ float sz[8][BT2][G2];     // 16 KB: per-k-slice gate partials
    __shared__ float slast[BT2][64];     // 1 KB
    __shared__ float sfc[BT2][64];       // 1 KB

    // weights: 4 gates x 20 k (combined) = 40 packed k-pairs (80 regs)
    ull wq[4][10];
#pragma unroll
    for (int g = 0; g < 4; g++) {
        const int gr = 4 * gq + g;
#pragma unroll
        for (int p = 0; p < 10; p++) {
            int kk = 20 * ks + 2 * p;
            float w0 = (kk < 128)     ? wih2f[gr * G2 + kk]
                                      : whh2f[gr * H2 + kk - 128];
            float w1 = (kk + 1 < 128) ? wih2f[gr * G2 + kk + 1]
                                      : whh2f[gr * H2 + kk + 1 - 128];
            wq[g][p] = pack2(w0, w1);
        }
    }
    float bs[4];
#pragma unroll
    for (int g = 0; g < 4; g++)
        bs[g] = (ks == 0) ? b2f[4 * gq + g] : 0.f;

    // zero h2 tails of both buffers
    if (tid < 128) {
        int b = tid >> 5, j = tid & 31;
        buf[0][b][128 + j] = 0.f;
        buf[1][b][128 + j] = 0.f;
    }
    // stage h1[t=0] tile (512 contiguous floats), float2 per thread
    const int pb = tid >> 6, pj = (tid & 63) * 2;
    {
        float2 v = *(const float2*)(g_h1 + (size_t)(b0 + pb) * 128 + pj);
        *(float2*)&buf[0][pb][pj] = v;
    }

    // cell states: tid<64 active. c0: batch cbl (A), c1: batch 2+cbl (B)
    float c0 = 0.f, c1 = 0.f;
    const int cbl = tid >> 5;           // 0..1 when tid<64
    const int chh = tid & 31;

    __syncthreads();

    for (int t = 0; t < TT; ++t) {
        const int cur = t & 1;

        float2 pre = make_float2(0.f, 0.f);
        if (t + 1 < TT)
            pre = *(const float2*)(g_h1 + ((size_t)(t + 1) * BB + b0 + pb) * 128 + pj);

        // ================= P1: cell(B, t-1) + FMA(A, t) =================
        if (t > 0 && tid < 64) {
            const int cb2 = 2 + cbl;
            float zi = 0.f, zf = 0.f, zg = 0.f, zo = 0.f;
#pragma unroll
            for (int s = 0; s < 8; s++) {
                zi += sz[s][cb2][chh];
                zf += sz[s][cb2][32 + chh];
                zg += sz[s][cb2][64 + chh];
                zo += sz[s][cb2][96 + chh];
            }
            c1 = sigm(zf) * c1 + sigm(zi) * tanh_(zg);
            float h2 = sigm(zo) * tanh_(c1);
            buf[0][cb2][128 + chh] = h2;
            buf[1][cb2][128 + chh] = h2;
        }
        {
            ull acc[4][2];   // [gate][batch]
#pragma unroll
            for (int b = 0; b < 2; b++)
#pragma unroll
                for (int g = 0; g < 4; g++) acc[g][b] = pack2(bs[g], 0.f);
#pragma unroll
            for (int j = 0; j < 5; j++) {
#pragma unroll
                for (int b = 0; b < 2; b++) {
                    ulonglong2 hv = *(const ulonglong2*)&buf[cur][b][20 * ks + 4 * j];
#pragma unroll
                    for (int g = 0; g < 4; g++) {
                        ffma2(acc[g][b], hv.x, wq[g][2 * j]);
                        ffma2(acc[g][b], hv.y, wq[g][2 * j + 1]);
                    }
                }
            }
#pragma unroll
            for (int b = 0; b < 2; b++) {
                float4 v = make_float4(hadd2(acc[0][b]), hadd2(acc[1][b]),
                                       hadd2(acc[2][b]), hadd2(acc[3][b]));
                *(float4*)&sz[ks][b][4 * gq] = v;
            }
        }
        if (t + 1 < TT) *(float2*)&buf[1 - cur][pb][pj] = pre;
        __syncthreads();

        // ================= P2: cell(A, t) + FMA(B, t) =================
        if (tid < 64) {
            float zi = 0.f, zf = 0.f, zg = 0.f, zo = 0.f;
#pragma unroll
            for (int s = 0; s < 8; s++) {
                zi += sz[s][cbl][chh];
                zf += sz[s][cbl][32 + chh];
                zg += sz[s][cbl][64 + chh];
                zo += sz[s][cbl][96 + chh];
            }
            c0 = sigm(zf) * c0 + sigm(zi) * tanh_(zg);
            float h2 = sigm(zo) * tanh_(c0);
            buf[0][cbl][128 + chh] = h2;
            buf[1][cbl][128 + chh] = h2;
        }
        {
            ull acc[4][2];
#pragma unroll
            for (int b = 0; b < 2; b++)
#pragma unroll
                for (int g = 0; g < 4; g++) acc[g][b] = pack2(bs[g], 0.f);
#pragma unroll
            for (int j = 0; j < 5; j++) {
#pragma unroll
                for (int b = 0; b < 2; b++) {
                    ulonglong2 hv = *(const ulonglong2*)&buf[cur][b + 2][20 * ks + 4 * j];
#pragma unroll
                    for (int g = 0; g < 4; g++) {
                        ffma2(acc[g][b], hv.x, wq[g][2 * j]);
                        ffma2(acc[g][b], hv.y, wq[g][2 * j + 1]);
                    }
                }
            }
#pragma unroll
            for (int b = 0; b < 2; b++) {
                float4 v = make_float4(hadd2(acc[0][b]), hadd2(acc[1][b]),
                                       hadd2(acc[2][b]), hadd2(acc[3][b]));
                *(float4*)&sz[ks][b + 2][4 * gq] = v;
            }
        }
        __syncthreads();
    }

    // epilogue: cell(B, TT-1)
    if (tid < 64) {
        const int cb2 = 2 + cbl;
        float zi = 0.f, zf = 0.f, zg = 0.f, zo = 0.f;
#pragma unroll
        for (int s = 0; s < 8; s++) {
            zi += sz[s][cb2][chh];
            zf += sz[s][cb2][32 + chh];
            zg += sz[s][cb2][64 + chh];
            zo += sz[s][cb2][96 + chh];
        }
        c1 = sigm(zf) * c1 + sigm(zi) * tanh_(zg);
        float h2 = sigm(zo) * tanh_(c1);
        buf[1][cb2][128 + chh] = h2;
    }
    __syncthreads();
    // buf[1][b][0..128) = h1[T-1]; buf[1][b][128..160) = final fwd h2.

    // layer-2 reverse: single step at t = T-1 from h=c=0.
    // thread = (g2 = tid&127, rb = tid>>7): batches 2*rb, 2*rb+1
    {
        const int g2 = tid & 127;
        const int rb = tid >> 7;
        const float brv = b2r[g2];
        float a0 = brv, a1 = brv;
        const float* wr = wih2r + g2 * G2;
        for (int k = 0; k < G2; k++) {
            float wv = __ldg(wr + k);
            a0 = fmaf(buf[1][2 * rb][k],     wv, a0);
            a1 = fmaf(buf[1][2 * rb + 1][k], wv, a1);
        }
        float* zr = (float*)sz;
        zr[2 * rb * G2 + g2]       = a0;
        zr[(2 * rb + 1) * G2 + g2] = a1;
    }
    __syncthreads();
    if (tid < 128) {
        const int cb4 = tid >> 5;       // 0..3
        const float* zr = (const float*)sz;
        float zi = zr[cb4 * G2 + chh];
        float zg = zr[cb4 * G2 + 64 + chh], zo = zr[cb4 * G2 + 96 + chh];
        float cr = sigm(zi) * tanh_(zg);      // c_prev = 0
        float hr = sigm(zo) * tanh_(cr);
        slast[cb4][chh]      = buf[1][cb4][128 + chh];
        slast[cb4][32 + chh] = hr;
    }
    __syncthreads();

    // fc1 (64x64) + relu: 256 items
    {
        int b = tid >> 6, o = tid & 63;
        float a = b_fc1[o];
        const float* wf = w_fc1 + o * 64;
        for (int k = 0; k < 64; k++) a = fmaf(slast[b][k], __ldg(wf + k), a);
        sfc[b][o] = fmaxf(a, 0.f);
    }
    __syncthreads();

    if (tid < BT2) {
        float a = b_out[0];
        for (int k = 0; k < 64; k++) a = fmaf(sfc[tid][k], __ldg(w_out + k), a);
        out[b0 + tid] = sigm(a);
    }
}

// ---------------------------------------------------------------------------
extern "C" void kernel_launch(void* const* d_in, const int* in_sizes, int n_in,
                              void* d_out, int out_size)
{
    (void)in_sizes; (void)n_in; (void)out_size;
    const float* x     = (const float*)d_in[0];
    const float* wih1f = (const float*)d_in[1];
    const float* whh1f = (const float*)d_in[2];
    const float* b1f   = (const float*)d_in[3];
    const float* wih1r = (const float*)d_in[4];
    const float* whh1r = (const float*)d_in[5];
    const float* b1r   = (const float*)d_in[6];
    const float* wih2f = (const float*)d_in[7];
    const float* whh2f = (const float*)d_in[8];
    const float* b2f   = (const float*)d_in[9];
    const float* wih2r = (const float*)d_in[10];
    const float* b2r   = (const float*)d_in[12];
    const float* w_fc1 = (const float*)d_in[13];
    const float* b_fc1 = (const float*)d_in[14];
    const float* w_out = (const float*)d_in[15];
    const float* b_out = (const float*)d_in[16];
    float* out = (float*)d_out;

    lstm1_kernel<<<dim3(BB / BT1, 2), 256>>>(x, wih1f, whh1f, b1f, wih1r, whh1r, b1r);
    lstm2_kernel<<<BB / BT2, 256>>>(wih2f, whh2f, b2f, wih2r, b2r,
                                    w_fc1, b_fc1, w_out, b_out, out);
}

// round 8
// speedup vs baseline: 1.0808x; 1.0808x over previous
#include <cuda_runtime.h>
#include <cstdint>

#define TT   512
#define BB   1024
#define H1   64
#define G1   256     // 4*H1
#define BT1  8
#define H2   32
#define G2   128     // 4*H2

typedef unsigned long long ull;

// scratch: h1[t][b][j], j in [0,128): fwd half [0,64), rev half [64,128)
__device__ float g_h1[(size_t)TT * BB * 128];
// precomputed layer-2 input projection + bias: xi[t][b][g], g in [0,128)
__device__ float g_xi[(size_t)TT * BB * 128];

// ---- fast activations -----------------------------------------------------
__device__ __forceinline__ float tanh_(float x) {
    float y;
    asm("tanh.approx.f32 %0, %1;" : "=f"(y) : "f"(x));
    return y;
}
__device__ __forceinline__ float sigm(float x) {
    return fmaf(tanh_(x * 0.5f), 0.5f, 0.5f);
}

// ---- packed fp32x2 fma ----------------------------------------------------
__device__ __forceinline__ void ffma2(ull& acc, ull a, ull b) {
    asm("fma.rn.f32x2 %0, %1, %2, %0;" : "+l"(acc) : "l"(a), "l"(b));
}
__device__ __forceinline__ ull pack2(float lo, float hi) {
    ull r;
    asm("mov.b64 %0, {%1, %2};" : "=l"(r) : "f"(lo), "f"(hi));
    return r;
}
__device__ __forceinline__ float hadd2(ull v) {
    float lo, hi;
    asm("mov.b64 {%0, %1}, %2;" : "=f"(lo), "=f"(hi) : "l"(v));
    return lo + hi;
}
__device__ __forceinline__ void unpk(ull v, float& lo, float& hi) {
    asm("mov.b64 {%0, %1}, %2;" : "=f"(lo), "=f"(hi) : "l"(v));
}

// ---------------------------------------------------------------------------
// Kernel 1: bidirectional layer-1 LSTM (unchanged from best round).
// grid = (128, 2), block = 256.  thread = (gp = tid&127, half = tid>>7).
// ---------------------------------------------------------------------------
__global__ __launch_bounds__(256, 2)
void lstm1_kernel(const float* __restrict__ x,
                  const float* __restrict__ wih_f, const float* __restrict__ whh_f,
                  const float* __restrict__ b_f,
                  const float* __restrict__ wih_r, const float* __restrict__ whh_r,
                  const float* __restrict__ b_r)
{
    const int dir  = blockIdx.y;
    const int b0   = blockIdx.x * BT1;
    const int tid  = threadIdx.x;
    const int gp   = tid & 127;
    const int half = tid >> 7;

    const float* wih = dir ? wih_r : wih_f;
    const float* whh = dir ? whh_r : whh_f;
    const float* bb  = dir ? b_r  : b_f;

    __shared__ float sxc[BT1][64];
    __shared__ float sh[BT1][H1];
    __shared__ float szA[BT1][G1];
    __shared__ float szB[BT1][G1];

    for (int i = tid; i < BT1 * H1; i += 256) ((float*)sh)[i] = 0.f;

    ull wp0[16], wp1[16];
    {
        const ull* w0 = (const ull*)(whh + (2 * gp)     * H1 + 32 * half);
        const ull* w1 = (const ull*)(whh + (2 * gp + 1) * H1 + 32 * half);
#pragma unroll
        for (int j = 0; j < 16; j++) { wp0[j] = w0[j]; wp1[j] = w1[j]; }
    }
    const float wi0 = (half == 0) ? wih[2 * gp]     : 0.f;
    const float wi1 = (half == 0) ? wih[2 * gp + 1] : 0.f;
    const float bg0 = (half == 0) ? bb[2 * gp]      : 0.f;
    const float bg1 = (half == 0) ? bb[2 * gp + 1]  : 0.f;

    float c0 = 0.f, c1 = 0.f;
    const int cb = tid >> 6;
    const int ch = tid & 63;

    float* dst = half ? &szB[0][0] : &szA[0][0];

    __syncthreads();

    for (int tt = 0; tt < TT; ++tt) {
        const int t = dir ? (TT - 1 - tt) : tt;

        if ((tt & 63) == 0) {
            const int tbase = dir ? (448 - tt) : tt;
            for (int i = tid; i < BT1 * 64; i += 256) {
                int b = i >> 6, to = i & 63;
                sxc[b][to] = x[(size_t)(b0 + b) * TT + tbase + to];
            }
            __syncthreads();
        }
        const int ts = t & 63;

        // P1: cell(B, t-1) + FMA(A, t)
        if (tt > 0) {
            const int tp  = dir ? (TT - tt) : (tt - 1);
            const int cb2 = cb + 4;
            float zi = szA[cb2][ch]       + szB[cb2][ch];
            float zf = szA[cb2][64 + ch]  + szB[cb2][64 + ch];
            float zg = szA[cb2][128 + ch] + szB[cb2][128 + ch];
            float zo = szA[cb2][192 + ch] + szB[cb2][192 + ch];
            c1 = sigm(zf) * c1 + sigm(zi) * tanh_(zg);
            float hv = sigm(zo) * tanh_(c1);
            sh[cb2][ch] = hv;
            g_h1[((size_t)tp * BB + (b0 + cb2)) * 128 + dir * 64 + ch] = hv;
        }
        {
            ull a0[4], a1[4];
            if (half == 0) {
#pragma unroll
                for (int b = 0; b < 4; b++) {
                    float xv = sxc[b][ts];
                    a0[b] = pack2(fmaf(xv, wi0, bg0), 0.f);
                    a1[b] = pack2(fmaf(xv, wi1, bg1), 0.f);
                }
            } else {
#pragma unroll
                for (int b = 0; b < 4; b++) { a0[b] = 0ULL; a1[b] = 0ULL; }
            }
#pragma unroll
            for (int j = 0; j < 8; j++) {
#pragma unroll
                for (int b = 0; b < 4; b++) {
                    ulonglong2 hv = *(const ulonglong2*)&sh[b][32 * half + 4 * j];
                    ffma2(a0[b], hv.x, wp0[2 * j]);
                    ffma2(a0[b], hv.y, wp0[2 * j + 1]);
                    ffma2(a1[b], hv.x, wp1[2 * j]);
                    ffma2(a1[b], hv.y, wp1[2 * j + 1]);
                }
            }
#pragma unroll
            for (int b = 0; b < 4; b++)
                *(ull*)(dst + b * G1 + 2 * gp) = pack2(hadd2(a0[b]), hadd2(a1[b]));
        }
        __syncthreads();

        // P2: cell(A, t) + FMA(B, t)
        {
            float zi = szA[cb][ch]       + szB[cb][ch];
            float zf = szA[cb][64 + ch]  + szB[cb][64 + ch];
            float zg = szA[cb][128 + ch] + szB[cb][128 + ch];
            float zo = szA[cb][192 + ch] + szB[cb][192 + ch];
            c0 = sigm(zf) * c0 + sigm(zi) * tanh_(zg);
            float hv = sigm(zo) * tanh_(c0);
            sh[cb][ch] = hv;
            g_h1[((size_t)t * BB + (b0 + cb)) * 128 + dir * 64 + ch] = hv;
        }
        {
            ull a0[4], a1[4];
            if (half == 0) {
#pragma unroll
                for (int b = 0; b < 4; b++) {
                    float xv = sxc[b + 4][ts];
                    a0[b] = pack2(fmaf(xv, wi0, bg0), 0.f);
                    a1[b] = pack2(fmaf(xv, wi1, bg1), 0.f);
                }
            } else {
#pragma unroll
                for (int b = 0; b < 4; b++) { a0[b] = 0ULL; a1[b] = 0ULL; }
            }
#pragma unroll
            for (int j = 0; j < 8; j++) {
#pragma unroll
                for (int b = 0; b < 4; b++) {
                    ulonglong2 hv = *(const ulonglong2*)&sh[b + 4][32 * half + 4 * j];
                    ffma2(a0[b], hv.x, wp0[2 * j]);
                    ffma2(a0[b], hv.y, wp0[2 * j + 1]);
                    ffma2(a1[b], hv.x, wp1[2 * j]);
                    ffma2(a1[b], hv.y, wp1[2 * j + 1]);
                }
            }
#pragma unroll
            for (int b = 0; b < 4; b++)
                *(ull*)(dst + (b + 4) * G1 + 2 * gp) = pack2(hadd2(a0[b]), hadd2(a1[b]));
        }
        __syncthreads();
    }

    {
        const int tp  = dir ? 0 : (TT - 1);
        const int cb2 = cb + 4;
        float zi = szA[cb2][ch]       + szB[cb2][ch];
        float zf = szA[cb2][64 + ch]  + szB[cb2][64 + ch];
        float zg = szA[cb2][128 + ch] + szB[cb2][128 + ch];
        float zo = szA[cb2][192 + ch] + szB[cb2][192 + ch];
        c1 = sigm(zf) * c1 + sigm(zi) * tanh_(zg);
        float hv = sigm(zo) * tanh_(c1);
        g_h1[((size_t)tp * BB + (b0 + cb2)) * 128 + dir * 64 + ch] = hv;
    }
}

// ---------------------------------------------------------------------------
// Kernel 2: xi = h1 @ Wih2f^T + b2f.   M = TT*BB rows, N = 128, K = 128.
// grid = M/128 = 4096 blocks, 256 threads.  Tile: 128m x 128n, k-chunks of 32.
// thread (ni = tid&15, mi = tid>>4) owns an 8m x 8n C sub-tile, m-paired.
// ---------------------------------------------------------------------------
__global__ __launch_bounds__(256, 2)
void xi_gemm_kernel(const float* __restrict__ W,     // wih2f [128][128]
                    const float* __restrict__ bias)  // b2f [128]
{
    const int tid   = threadIdx.x;
    const int mbase = blockIdx.x * 128;
    const int ni    = tid & 15;
    const int mi    = tid >> 4;
    const int n0    = ni * 8;
    const int m0    = mi * 8;

    __shared__ float As[32][132];   // [k][m], padded
    __shared__ float Ws[32][132];   // [k][n], padded

    // accumulators: 4 m-pairs x 8 n, init with bias (same n for both m lanes)
    ull acc[4][8];
#pragma unroll
    for (int n = 0; n < 8; n++) {
        float bv = bias[n0 + n];
#pragma unroll
        for (int mp = 0; mp < 4; mp++) acc[mp][n] = pack2(bv, bv);
    }

    const int lr = tid & 127;       // row (m or n) this thread loads
    const int kh = tid >> 7;        // k-half of the chunk (16 each)

    for (int kc = 0; kc < 128; kc += 32) {
        __syncthreads();
        // stage W chunk: Ws[k][n] = W[n][kc+k]
        {
            const float4* src = (const float4*)(W + lr * 128 + kc + kh * 16);
#pragma unroll
            for (int i = 0; i < 4; i++) {
                float4 v = src[i];
                Ws[kh * 16 + 4 * i + 0][lr] = v.x;
                Ws[kh * 16 + 4 * i + 1][lr] = v.y;
                Ws[kh * 16 + 4 * i + 2][lr] = v.z;
                Ws[kh * 16 + 4 * i + 3][lr] = v.w;
            }
        }
        // stage A chunk: As[k][m] = h1[(mbase+m)][kc+k]
        {
            const float4* src = (const float4*)(g_h1 + (size_t)(mbase + lr) * 128 + kc + kh * 16);
#pragma unroll
            for (int i = 0; i < 4; i++) {
                float4 v = src[i];
                As[kh * 16 + 4 * i + 0][lr] = v.x;
                As[kh * 16 + 4 * i + 1][lr] = v.y;
                As[kh * 16 + 4 * i + 2][lr] = v.z;
                As[kh * 16 + 4 * i + 3][lr] = v.w;
            }
        }
        __syncthreads();

#pragma unroll 8
        for (int k = 0; k < 32; k++) {
            float4 a0 = *(const float4*)&As[k][m0];
            float4 a1 = *(const float4*)&As[k][m0 + 4];
            float4 w0 = *(const float4*)&Ws[k][n0];
            float4 w1 = *(const float4*)&Ws[k][n0 + 4];
            ull ap[4];
            ap[0] = pack2(a0.x, a0.y); ap[1] = pack2(a0.z, a0.w);
            ap[2] = pack2(a1.x, a1.y); ap[3] = pack2(a1.z, a1.w);
            float wv[8] = {w0.x, w0.y, w0.z, w0.w, w1.x, w1.y, w1.z, w1.w};
#pragma unroll
            for (int n = 0; n < 8; n++) {
                ull wd = pack2(wv[n], wv[n]);
#pragma unroll
                for (int mp = 0; mp < 4; mp++) ffma2(acc[mp][n], ap[mp], wd);
            }
        }
    }

    // write back: rows m0+2mp, m0+2mp+1; 8 consecutive n each -> 2 STG.128/row
#pragma unroll
    for (int mp = 0; mp < 4; mp++) {
        float r0[8], r1[8];
#pragma unroll
        for (int n = 0; n < 8; n++) unpk(acc[mp][n], r0[n], r1[n]);
        float* d0 = g_xi + (size_t)(mbase + m0 + 2 * mp) * 128 + n0;
        float* d1 = d0 + 128;
        *(float4*)(d0)     = make_float4(r0[0], r0[1], r0[2], r0[3]);
        *(float4*)(d0 + 4) = make_float4(r0[4], r0[5], r0[6], r0[7]);
        *(float4*)(d1)     = make_float4(r1[0], r1[1], r1[2], r1[3]);
        *(float4*)(d1 + 4) = make_float4(r1[4], r1[5], r1[6], r1[7]);
    }
}

// ---------------------------------------------------------------------------
// Kernel 3: layer-2 recurrent scan (warp per batch, no block barriers in loop)
// + single reverse step + MLP head.
// grid = 128, block = 256 (8 warps = 8 batches). Lane j owns cell j:
// gates j, 32+j, 64+j, 96+j.  Weights Whh2f rows in regs, k-paired.
// ---------------------------------------------------------------------------
__global__ __launch_bounds__(256, 1)
void lstm2_scan_kernel(const float* __restrict__ whh2f,
                       const float* __restrict__ wih2r, const float* __restrict__ b2r,
                       const float* __restrict__ w_fc1, const float* __restrict__ b_fc1,
                       const float* __restrict__ w_out, const float* __restrict__ b_out,
                       float* __restrict__ out)
{
    const int b0  = blockIdx.x * 8;
    const int tid = threadIdx.x;
    const int w   = tid >> 5;          // warp = local batch
    const int j   = tid & 31;          // cell index
    const int bb  = b0 + w;

    __shared__ float shh[8][32];       // per-warp h (current)
    __shared__ float h1last[8][128];   // h1[T-1] rows (for reverse step)
    __shared__ float zrev[8][128];
    __shared__ float slast[8][64];
    __shared__ float sfc[8][64];

    // recurrent weights: 4 gates x 32 k, k-paired (64 ull)
    ull wq[4][16];
#pragma unroll
    for (int q = 0; q < 4; q++) {
        const ull* wr = (const ull*)(whh2f + (q * 32 + j) * H2);
#pragma unroll
        for (int p = 0; p < 16; p++) wq[q][p] = wr[p];
    }

    shh[w][j] = 0.f;
    float c = 0.f, hmine = 0.f;

    // first xi load (t = 0)
    const float* xibase = g_xi + (size_t)bb * 128 + j;
    float xin[4];
#pragma unroll
    for (int q = 0; q < 4; q++) xin[q] = xibase[q * 32];

    __syncwarp();

    for (int t = 0; t < TT; ++t) {
        // prefetch xi for t+1
        float xnx[4] = {0.f, 0.f, 0.f, 0.f};
        if (t + 1 < TT) {
            const float* p = xibase + (size_t)(t + 1) * BB * 128;
#pragma unroll
            for (int q = 0; q < 4; q++) xnx[q] = p[q * 32];
        }

        ull acc[4];
#pragma unroll
        for (int q = 0; q < 4; q++) acc[q] = pack2(xin[q], 0.f);

#pragma unroll
        for (int p = 0; p < 16; p++) {
            ull hv = *(const ull*)&shh[w][2 * p];    // broadcast LDS.64
#pragma unroll
            for (int q = 0; q < 4; q++) ffma2(acc[q], hv, wq[q][p]);
        }
        float zi = hadd2(acc[0]);
        float zf = hadd2(acc[1]);
        float zg = hadd2(acc[2]);
        float zo = hadd2(acc[3]);
        c = sigm(zf) * c + sigm(zi) * tanh_(zg);
        hmine = sigm(zo) * tanh_(c);

        __syncwarp();                  // all lanes done reading old h
        shh[w][j] = hmine;
        __syncwarp();                  // new h visible

#pragma unroll
        for (int q = 0; q < 4; q++) xin[q] = xnx[q];
    }
    // shh[w][j] = final forward h2.

    __syncthreads();

    // stage h1[T-1] rows for this block's 8 batches
    {
        int idx = tid * 4;                 // 1024 floats total
        int b = idx >> 7, k = idx & 127;
        *(float4*)&h1last[b][k] =
            *(const float4*)(g_h1 + ((size_t)(TT - 1) * BB + b0 + b) * 128 + k);
    }
    __syncthreads();

    // reverse single step: z = Wih2r @ h1last + b2r  (c_prev = h_prev = 0)
    {
        const int g2 = tid & 127;
        const int hf = tid >> 7;           // batch half: 4 batches each
        const float brv = b2r[g2];
        float a[4] = {brv, brv, brv, brv};
        const float* wr = wih2r + g2 * G2;
        for (int k = 0; k < G2; k++) {
            float wv = __ldg(wr + k);
#pragma unroll
            for (int b = 0; b < 4; b++)
                a[b] = fmaf(h1last[hf * 4 + b][k], wv, a[b]);
        }
#pragma unroll
        for (int b = 0; b < 4; b++) zrev[hf * 4 + b][g2] = a[b];
    }
    __syncthreads();
    {
        const int b = tid >> 5, jj = tid & 31;
        float zi = zrev[b][jj];
        float zg = zrev[b][64 + jj], zo = zrev[b][96 + jj];
        float cr = sigm(zi) * tanh_(zg);
        float hr = sigm(zo) * tanh_(cr);
        slast[b][jj]      = shh[b][jj];    // forward half
        slast[b][32 + jj] = hr;            // reverse half
    }
    __syncthreads();

    // fc1 (64x64) + relu: 512 items, 2 per thread
#pragma unroll
    for (int rep = 0; rep < 2; rep++) {
        int item = tid + rep * 256;
        int b = item >> 6, o = item & 63;
        float a = b_fc1[o];
        const float* wf = w_fc1 + o * 64;
        for (int k = 0; k < 64; k++) a = fmaf(slast[b][k], __ldg(wf + k), a);
        sfc[b][o] = fmaxf(a, 0.f);
    }
    __syncthreads();

    if (tid < 8) {
        float a = b_out[0];
        for (int k = 0; k < 64; k++) a = fmaf(sfc[tid][k], __ldg(w_out + k), a);
        out[b0 + tid] = sigm(a);
    }
}

// ---------------------------------------------------------------------------
extern "C" void kernel_launch(void* const* d_in, const int* in_sizes, int n_in,
                              void* d_out, int out_size)
{
    (void)in_sizes; (void)n_in; (void)out_size;
    const float* x     = (const float*)d_in[0];
    const float* wih1f = (const float*)d_in[1];
    const float* whh1f = (const float*)d_in[2];
    const float* b1f   = (const float*)d_in[3];
    const float* wih1r = (const float*)d_in[4];
    const float* whh1r = (const float*)d_in[5];
    const float* b1r   = (const float*)d_in[6];
    const float* wih2f = (const float*)d_in[7];
    const float* whh2f = (const float*)d_in[8];
    const float* b2f   = (const float*)d_in[9];
    const float* wih2r = (const float*)d_in[10];
    const float* b2r   = (const float*)d_in[12];
    const float* w_fc1 = (const float*)d_in[13];
    const float* b_fc1 = (const float*)d_in[14];
    const float* w_out = (const float*)d_in[15];
    const float* b_out = (const float*)d_in[16];
    float* out = (float*)d_out;

    lstm1_kernel<<<dim3(BB / BT1, 2), 256>>>(x, wih1f, whh1f, b1f, wih1r, whh1r, b1r);
    xi_gemm_kernel<<<(TT * BB) / 128, 256>>>(wih2f, b2f);
    lstm2_scan_kernel<<<BB / 8, 256>>>(whh2f, wih2r, b2r,
                                       w_fc1, b_fc1, w_out, b_out, out);
}